// round 5
// baseline (speedup 1.0000x reference)
#include <cuda_runtime.h>

#define B_    8
#define CIN   32
#define CMID  16
#define COUT  32
#define Hdim  384
#define Wdim  384
#define NTAPS 25
#define TILE_H 24
#define TILE_W 32
#define TH (TILE_H + 6)   // 30
#define TW (TILE_W + 6)   // 38
#define NTHR 384

typedef unsigned long long ull;

// ---------------- scratch (__device__ globals; no allocation) ----------------
// per (b,k): [0]=full sum, [1..6]=row sums (rows 0,1,2,H-3,H-2,H-1),
// [7..12]=col sums (same col set), [13..48]=corner elems x[rset[i], cset[j]] (6x6)
__device__ float statsG[B_ * CIN * 49];
__device__ float WG[NTAPS * CIN * CMID];   // combined softmax-weighted tap weights [t][k][c]
__device__ float betaG[B_ * CMID];         // per-(b,c) constant of T
__device__ float AG[B_ * COUT * CMID];     // folded epilogue weights fusion_w[o,c]*g[b,c]

__constant__ int TAPY[NTAPS] = {0, -1,-1,-1, 0, 0, 1, 1, 1,
                                   -2,-2,-2, 0, 0, 2, 2, 2,
                                   -3,-3,-3, 0, 0, 3, 3, 3};
__constant__ int TAPX[NTAPS] = {0, -1, 0, 1,-1, 1,-1, 0, 1,
                                   -2, 0, 2,-2, 2,-2, 0, 2,
                                   -3, 0, 3,-3, 3,-3, 0, 3};

// ---------------- f32x2 helpers (FFMA2 — PTX only, full-rate FMA pipe) ------
__device__ __forceinline__ ull pack2(float a, float b) {
    ull r; asm("mov.b64 %0, {%1,%2};" : "=l"(r) : "f"(a), "f"(b)); return r;
}
__device__ __forceinline__ void fma2(ull& d, ull a, ull b) {
    asm("fma.rn.f32x2 %0, %1, %2, %0;" : "+l"(d) : "l"(a), "l"(b));
}
__device__ __forceinline__ float2 unpack2(ull v) {
    float2 f; asm("mov.b64 {%0,%1}, %2;" : "=f"(f.x), "=f"(f.y) : "l"(v)); return f;
}

// ================= Kernel A: per-(b,k) plane statistics ======================
__global__ void stats_kernel(const float* __restrict__ x) {
    const int bk  = blockIdx.x;                 // b*32+k
    const float* p = x + (size_t)bk * Hdim * Wdim;
    float* st = statsG + bk * 49;
    const int tid = threadIdx.x;
    __shared__ float red[256];

    const int RI[6] = {0, 1, 2, Hdim - 3, Hdim - 2, Hdim - 1};

    // full sum (deterministic tree reduce)
    float s = 0.f;
    for (int i = tid; i < Hdim * Wdim; i += 256) s += p[i];
    red[tid] = s; __syncthreads();
    for (int d = 128; d > 0; d >>= 1) {
        if (tid < d) red[tid] += red[tid + d];
        __syncthreads();
    }
    if (tid == 0) st[0] = red[0];
    __syncthreads();

    // 6 border row sums
    for (int j = 0; j < 6; j++) {
        float rs = 0.f;
        for (int wv = tid; wv < Wdim; wv += 256) rs += p[RI[j] * Wdim + wv];
        red[tid] = rs; __syncthreads();
        for (int d = 128; d > 0; d >>= 1) {
            if (tid < d) red[tid] += red[tid + d];
            __syncthreads();
        }
        if (tid == 0) st[1 + j] = red[0];
        __syncthreads();
    }
    // 6 border col sums
    for (int j = 0; j < 6; j++) {
        float cs = 0.f;
        for (int h = tid; h < Hdim; h += 256) cs += p[h * Wdim + RI[j]];
        red[tid] = cs; __syncthreads();
        for (int d = 128; d > 0; d >>= 1) {
            if (tid < d) red[tid] += red[tid + d];
            __syncthreads();
        }
        if (tid == 0) st[7 + j] = red[0];
        __syncthreads();
    }
    // 36 corner elements
    if (tid < 36) {
        int i = tid / 6, j = tid % 6;
        st[13 + tid] = p[RI[i] * Wdim + RI[j]];
    }
}

// exact spatial sum of zero-padded shifted plane: sum_{h,w} xpad[h+oy, w+ox]
__device__ __forceinline__ float rectsum(const float* st, int oy, int ox) {
    float s = st[0];
    int r0, r1, c0, c1;
    if (oy > 0)      { r0 = 0;      r1 = oy; }
    else if (oy < 0) { r0 = 6 + oy; r1 = 6;  }
    else             { r0 = 0;      r1 = 0;  }
    if (ox > 0)      { c0 = 0;      c1 = ox; }
    else if (ox < 0) { c0 = 6 + ox; c1 = 6;  }
    else             { c0 = 0;      c1 = 0;  }
    for (int i = r0; i < r1; i++) s -= st[1 + i];
    for (int j = c0; j < c1; j++) s -= st[7 + j];
    for (int i = r0; i < r1; i++)
        for (int j = c0; j < c1; j++) s += st[13 + i * 6 + j];
    return s;
}

// ================= Kernel B: tiny prep (softmax, g, beta, A, combined W) =====
__global__ void prep_kernel(
    const float* __restrict__ w1, const float* __restrict__ b1,
    const float* __restrict__ w2, const float* __restrict__ b2,
    const float* __restrict__ w3, const float* __restrict__ b3,
    const float* __restrict__ w4, const float* __restrict__ b4,
    const float* __restrict__ w5, const float* __restrict__ b5,
    const float* __restrict__ gcn_w, const float* __restrict__ gcn_b,
    const float* __restrict__ attn,
    const float* __restrict__ fw)
{
    __shared__ float mg[B_][CMID];
    __shared__ float sw[5];
    const int tid = threadIdx.x;   // 128 threads = B_*CMID

    if (tid == 0) {
        float mx = attn[0];
        for (int i = 1; i < 5; i++) mx = fmaxf(mx, attn[i]);
        float e[5], se = 0.f;
        for (int i = 0; i < 5; i++) { e[i] = expf(attn[i] - mx); se += e[i]; }
        for (int i = 0; i < 5; i++) sw[i] = e[i] / se;
    }
    __syncthreads();

    const int b = tid >> 4, c = tid & 15;
    const float inv = 1.f / (float)(Hdim * Wdim);
    const float* wj[3] = {w2, w3, w4};

    // f5[b,c] = w5 @ gap + b5   (gap = full-sum / HW)
    float f5 = b5[c];
    for (int k = 0; k < CIN; k++)
        f5 += w5[c * CIN + k] * statsG[(b * CIN + k) * 49] * inv;

    // branch node means (exact, incl. zero-pad boundary effects)
    float nm0 = b1[c];
    for (int k = 0; k < CIN; k++)
        nm0 += w1[c * CIN + k] * statsG[(b * CIN + k) * 49] * inv;

    float nmd[3] = {b2[c], b3[c], b4[c]};
    for (int d = 1; d <= 3; d++) {
        float acc = 0.f;
        for (int k = 0; k < CIN; k++) {
            const float* st = &statsG[(b * CIN + k) * 49];
            for (int dy = 0; dy < 3; dy++)
                for (int dx = 0; dx < 3; dx++) {
                    float wv = wj[d - 1][((c * CIN + k) * 3 + dy) * 3 + dx];
                    acc += wv * rectsum(st, (dy - 1) * d, (dx - 1) * d);
                }
        }
        nmd[d - 1] += acc * inv;
    }

    mg[b][c] = (nm0 + nmd[0] + nmd[1] + nmd[2] + f5) * 0.2f;

    // beta[b,c] = sum_i sw_i * (branch constant)
    betaG[b * CMID + c] = sw[0] * b1[c] + sw[1] * b2[c] + sw[2] * b3[c]
                        + sw[3] * b4[c] + sw[4] * f5;
    __syncthreads();

    // g[b,c] = mg @ gcn_w + gcn_b ;  fold into A[b,o,c] = fusion_w[o,c]*g[b,c]
    float g = gcn_b[c];
    for (int cp = 0; cp < CMID; cp++) g += mg[b][cp] * gcn_w[cp * CMID + c];
    for (int o = 0; o < COUT; o++)
        AG[(b * COUT + o) * CMID + c] = fw[o * CMID + c] * g;

    // combined softmax-weighted 25-tap weights (batch independent)
    for (int i = tid; i < NTAPS * CIN * CMID; i += 128) {
        int t  = i / (CIN * CMID);
        int rem = i - t * (CIN * CMID);
        int k  = rem / CMID;
        int cc = rem - k * CMID;
        int oy = TAPY[t], ox = TAPX[t];
        float v = 0.f;
        if (t == 0) v += sw[0] * w1[cc * CIN + k];           // 1x1 branch at center
        for (int d = 1; d <= 3; d++) {
            bool okY = (oy == 0) || (oy == d) || (oy == -d);
            bool okX = (ox == 0) || (ox == d) || (ox == -d);
            if (okY && okX) {
                int dy = oy / d + 1, dx = ox / d + 1;
                v += sw[d] * wj[d - 1][((cc * CIN + k) * 3 + dy) * 3 + dx];
            }
        }
        WG[i] = v;
    }
}

// ================= Kernel C: fused 25-tap conv + folded 1x1 epilogue =========
// smem layout (bytes): xs @0 (145920), ws @145920 (51200), As @197120 (2048),
// betas @199168 (64), fbs @199232 (128)  => total 199360
#define SMEM_XS_OFF   0
#define SMEM_WS_OFF   145920
#define SMEM_AS_OFF   197120
#define SMEM_BETA_OFF 199168
#define SMEM_FB_OFF   199232
#define SMEM_TOTAL    199360

__global__ void __launch_bounds__(NTHR, 1)
conv_kernel(const float* __restrict__ x, const float* __restrict__ fbias,
            float* __restrict__ out)
{
    extern __shared__ __align__(16) char smem[];
    float* xs    = (float*)(smem + SMEM_XS_OFF);     // [CIN][TH][TW]
    float* wsh   = (float*)(smem + SMEM_WS_OFF);     // [NTAPS][CIN][CMID]
    float* As    = (float*)(smem + SMEM_AS_OFF);     // [COUT][CMID]
    float* betas = (float*)(smem + SMEM_BETA_OFF);
    float* fbs   = (float*)(smem + SMEM_FB_OFF);

    const int b   = blockIdx.z;
    const int bh0 = blockIdx.y * TILE_H;
    const int bw0 = blockIdx.x * TILE_W;
    const int tid = threadIdx.x;

    for (int i = tid; i < NTAPS * CIN * CMID; i += NTHR) wsh[i] = WG[i];
    for (int i = tid; i < COUT * CMID; i += NTHR)       As[i]  = AG[b * COUT * CMID + i];
    if (tid < CMID) betas[tid] = betaG[b * CMID + tid];
    if (tid < COUT) fbs[tid]   = fbias[tid];

    const float* xb = x + (size_t)b * CIN * Hdim * Wdim;
    for (int i = tid; i < CIN * TH * TW; i += NTHR) {
        int k   = i / (TH * TW);
        int rem = i - k * (TH * TW);
        int r   = rem / TW;
        int cc  = rem - r * TW;
        int gh = bh0 - 3 + r, gw = bw0 - 3 + cc;
        float v = 0.f;
        if ((unsigned)gh < Hdim && (unsigned)gw < Wdim)
            v = xb[(size_t)k * Hdim * Wdim + gh * Wdim + gw];
        xs[i] = v;
    }
    __syncthreads();

    const int w  = tid & 31;    // pixel column in tile
    const int hp = tid >> 5;    // 0..11 -> rows 2*hp, 2*hp+1
    const int h0 = hp * 2;

    ull acc0[8], acc1[8];       // channel-pair f32x2 accumulators, 2 pixels
#pragma unroll
    for (int p = 0; p < 8; p++) { acc0[p] = 0ULL; acc1[p] = 0ULL; }

    const float* xbase = xs + (h0 + 3) * TW + (w + 3);

#pragma unroll 1
    for (int t = 0; t < NTAPS; t++) {
        const float* xp = xbase + TAPY[t] * TW + TAPX[t];
        const ull*   wp = (const ull*)(wsh + t * (CIN * CMID));
#pragma unroll 4
        for (int k = 0; k < CIN; k++) {
            float xa = xp[k * (TH * TW)];
            float xc = xp[k * (TH * TW) + TW];
            ull xav = pack2(xa, xa);
            ull xcv = pack2(xc, xc);
            const ull* wk = wp + k * 8;
#pragma unroll
            for (int p = 0; p < 8; p++) {
                ull wv = wk[p];
                fma2(acc0[p], xav, wv);
                fma2(acc1[p], xcv, wv);
            }
        }
    }

    // T = acc + beta, then folded per-batch 1x1: out[o] = fb[o] + sum_c A[o,c]*T[c]
    float T0[CMID], T1[CMID];
#pragma unroll
    for (int p = 0; p < 8; p++) {
        float2 f0 = unpack2(acc0[p]);
        float2 f1 = unpack2(acc1[p]);
        T0[2 * p]     = f0.x + betas[2 * p];
        T0[2 * p + 1] = f0.y + betas[2 * p + 1];
        T1[2 * p]     = f1.x + betas[2 * p];
        T1[2 * p + 1] = f1.y + betas[2 * p + 1];
    }

    float* ob = out + (size_t)b * COUT * Hdim * Wdim;
    const int gh = bh0 + h0, gw = bw0 + w;
#pragma unroll 4
    for (int o = 0; o < COUT; o++) {
        float a0 = fbs[o], a1 = a0;
        const float* Ao = As + o * CMID;
#pragma unroll
        for (int c = 0; c < CMID; c++) {
            float av = Ao[c];
            a0 = fmaf(av, T0[c], a0);
            a1 = fmaf(av, T1[c], a1);
        }
        ob[(size_t)o * Hdim * Wdim + (size_t)gh * Wdim + gw]       = a0;
        ob[(size_t)o * Hdim * Wdim + (size_t)(gh + 1) * Wdim + gw] = a1;
    }
}

// ================= launch ====================================================
extern "C" void kernel_launch(void* const* d_in, const int* in_sizes, int n_in,
                              void* d_out, int out_size) {
    (void)in_sizes; (void)n_in; (void)out_size;
    const float* x     = (const float*)d_in[0];
    const float* w1    = (const float*)d_in[1];
    const float* b1    = (const float*)d_in[2];
    const float* w2    = (const float*)d_in[3];
    const float* b2    = (const float*)d_in[4];
    const float* w3    = (const float*)d_in[5];
    const float* b3    = (const float*)d_in[6];
    const float* w4    = (const float*)d_in[7];
    const float* b4    = (const float*)d_in[8];
    const float* w5    = (const float*)d_in[9];
    const float* b5    = (const float*)d_in[10];
    const float* gcn_w = (const float*)d_in[11];
    const float* gcn_b = (const float*)d_in[12];
    const float* attn  = (const float*)d_in[13];
    const float* fw    = (const float*)d_in[14];
    const float* fb    = (const float*)d_in[15];
    float* out = (float*)d_out;

    cudaFuncSetAttribute(conv_kernel,
                         cudaFuncAttributeMaxDynamicSharedMemorySize, SMEM_TOTAL);

    stats_kernel<<<B_ * CIN, 256>>>(x);
    prep_kernel<<<1, 128>>>(w1, b1, w2, b2, w3, b3, w4, b4, w5, b5,
                            gcn_w, gcn_b, attn, fw);
    dim3 grid(Wdim / TILE_W, Hdim / TILE_H, B_);   // 12 x 16 x 8
    conv_kernel<<<grid, NTHR, SMEM_TOTAL>>>(x, fb, out);
}

// round 7
// speedup vs baseline: 1.4949x; 1.4949x over previous
#include <cuda_runtime.h>

#define B_    8
#define CIN   32
#define CMID  16
#define COUT  32
#define Hdim  384
#define Wdim  384
#define HW    (Hdim * Wdim)
#define NTAPS 25
#define KHALF 16

#define TILE_H 32
#define TILE_W 48
#define TH (TILE_H + 6)   // 38
#define TWS (TILE_W + 6)  // 54
#define NTHR 384

typedef unsigned long long ull;

// ---------------- scratch (__device__ globals; no allocation) ----------------
// per (b,k): [0]=full sum, [1..6]=row sums (rows 0,1,2,H-3,H-2,H-1),
// [7..12]=col sums (same set), [13..48]=corner elems (6x6)
__device__ float statsG[B_ * CIN * 49];
__device__ float WG[NTAPS * CIN * CMID];   // combined softmax-weighted tap weights [t][k][c]
__device__ float betaG[B_ * CMID];         // per-(b,c) constant of T
__device__ float AG[B_ * COUT * CMID];     // folded epilogue weights fusion_w[o,c]*g[b,c]

__constant__ int TAPY[NTAPS] = {0, -1,-1,-1, 0, 0, 1, 1, 1,
                                   -2,-2,-2, 0, 0, 2, 2, 2,
                                   -3,-3,-3, 0, 0, 3, 3, 3};
__constant__ int TAPX[NTAPS] = {0, -1, 0, 1,-1, 1,-1, 0, 1,
                                   -2, 0, 2,-2, 2,-2, 0, 2,
                                   -3, 0, 3,-3, 3,-3, 0, 3};

// ---------------- f32x2 helpers (FFMA2 — PTX only) ---------------------------
__device__ __forceinline__ ull pack1(float a) {
    ull r; asm("mov.b64 %0, {%1,%1};" : "=l"(r) : "f"(a)); return r;
}
__device__ __forceinline__ void fma2(ull& d, ull a, ull b) {
    asm("fma.rn.f32x2 %0, %1, %2, %0;" : "+l"(d) : "l"(a), "l"(b));
}
__device__ __forceinline__ void add2(ull& d, ull a) {
    asm("add.rn.f32x2 %0, %0, %1;" : "+l"(d) : "l"(a));
}
__device__ __forceinline__ float2 unpack2(ull v) {
    float2 f; asm("mov.b64 {%0,%1}, %2;" : "=f"(f.x), "=f"(f.y) : "l"(v)); return f;
}

// ================= Kernel A: per-(b,k) plane statistics ======================
__global__ void __launch_bounds__(512)
stats_kernel(const float* __restrict__ x) {
    const int bk  = blockIdx.x;                 // b*32+k
    const float* p = x + (size_t)bk * HW;
    float* st = statsG + bk * 49;
    const int tid  = threadIdx.x;
    const int wid  = tid >> 5;
    const int lane = tid & 31;
    __shared__ float red[512];

    const int RI[6] = {0, 1, 2, Hdim - 3, Hdim - 2, Hdim - 1};

    // full sum: float4 loads, deterministic tree reduce
    const float4* p4 = (const float4*)p;
    float s = 0.f;
    for (int i = tid; i < HW / 4; i += 512) {
        float4 v = p4[i];
        s += (v.x + v.y) + (v.z + v.w);
    }
    red[tid] = s; __syncthreads();
    for (int d = 256; d > 0; d >>= 1) {
        if (tid < d) red[tid] += red[tid + d];
        __syncthreads();
    }
    if (tid == 0) st[0] = red[0];

    // 12 border sums: one warp each (warps 0..11), shfl reduce (deterministic)
    if (wid < 6) {                      // row sums
        float rs = 0.f;
        const float* row = p + RI[wid] * Wdim;
        for (int wv = lane; wv < Wdim; wv += 32) rs += row[wv];
        for (int d = 16; d > 0; d >>= 1)
            rs += __shfl_xor_sync(0xFFFFFFFF, rs, d);
        if (lane == 0) st[1 + wid] = rs;
    } else if (wid < 12) {              // col sums
        int j = wid - 6;
        float cs = 0.f;
        for (int h = lane; h < Hdim; h += 32) cs += p[h * Wdim + RI[j]];
        for (int d = 16; d > 0; d >>= 1)
            cs += __shfl_xor_sync(0xFFFFFFFF, cs, d);
        if (lane == 0) st[7 + j] = cs;
    } else if (wid == 14 && lane < 32) { // corners (36 elems -> lanes of warps 14/15)
        if (lane < 32) {
            int t = lane;
            if (t < 36) st[13 + t] = p[RI[t / 6] * Wdim + RI[t % 6]];
        }
    } else if (wid == 15 && lane < 4) {
        int t = 32 + lane;
        st[13 + t] = p[RI[t / 6] * Wdim + RI[t % 6]];
    }
}

// exact spatial sum of zero-padded shifted plane
__device__ __forceinline__ float rectsum(const float* st, int oy, int ox) {
    float s = st[0];
    int r0, r1, c0, c1;
    if (oy > 0)      { r0 = 0;      r1 = oy; }
    else if (oy < 0) { r0 = 6 + oy; r1 = 6;  }
    else             { r0 = 0;      r1 = 0;  }
    if (ox > 0)      { c0 = 0;      c1 = ox; }
    else if (ox < 0) { c0 = 6 + ox; c1 = 6;  }
    else             { c0 = 0;      c1 = 0;  }
    for (int i = r0; i < r1; i++) s -= st[1 + i];
    for (int j = c0; j < c1; j++) s -= st[7 + j];
    for (int i = r0; i < r1; i++)
        for (int j = c0; j < c1; j++) s += st[13 + i * 6 + j];
    return s;
}

// ================= Kernel B: tiny prep (softmax, g, beta, A, combined W) =====
__global__ void prep_kernel(
    const float* __restrict__ w1, const float* __restrict__ b1,
    const float* __restrict__ w2, const float* __restrict__ b2,
    const float* __restrict__ w3, const float* __restrict__ b3,
    const float* __restrict__ w4, const float* __restrict__ b4,
    const float* __restrict__ w5, const float* __restrict__ b5,
    const float* __restrict__ gcn_w, const float* __restrict__ gcn_b,
    const float* __restrict__ attn,
    const float* __restrict__ fw)
{
    __shared__ float mg[B_][CMID];
    __shared__ float sw[5];
    const int tid = threadIdx.x;   // 128 threads = B_*CMID

    if (tid == 0) {
        float mx = attn[0];
        for (int i = 1; i < 5; i++) mx = fmaxf(mx, attn[i]);
        float e[5], se = 0.f;
        for (int i = 0; i < 5; i++) { e[i] = expf(attn[i] - mx); se += e[i]; }
        for (int i = 0; i < 5; i++) sw[i] = e[i] / se;
    }
    __syncthreads();

    const int b = tid >> 4, c = tid & 15;
    const float inv = 1.f / (float)HW;
    const float* wj[3] = {w2, w3, w4};

    float f5 = b5[c];
    for (int k = 0; k < CIN; k++)
        f5 += w5[c * CIN + k] * statsG[(b * CIN + k) * 49] * inv;

    float nm0 = b1[c];
    for (int k = 0; k < CIN; k++)
        nm0 += w1[c * CIN + k] * statsG[(b * CIN + k) * 49] * inv;

    float nmd[3] = {b2[c], b3[c], b4[c]};
    for (int d = 1; d <= 3; d++) {
        float acc = 0.f;
        for (int k = 0; k < CIN; k++) {
            const float* st = &statsG[(b * CIN + k) * 49];
            for (int dy = 0; dy < 3; dy++)
                for (int dx = 0; dx < 3; dx++) {
                    float wv = wj[d - 1][((c * CIN + k) * 3 + dy) * 3 + dx];
                    acc += wv * rectsum(st, (dy - 1) * d, (dx - 1) * d);
                }
        }
        nmd[d - 1] += acc * inv;
    }

    mg[b][c] = (nm0 + nmd[0] + nmd[1] + nmd[2] + f5) * 0.2f;

    betaG[b * CMID + c] = sw[0] * b1[c] + sw[1] * b2[c] + sw[2] * b3[c]
                        + sw[3] * b4[c] + sw[4] * f5;
    __syncthreads();

    float g = gcn_b[c];
    for (int cp = 0; cp < CMID; cp++) g += mg[b][cp] * gcn_w[cp * CMID + c];
    for (int o = 0; o < COUT; o++)
        AG[(b * COUT + o) * CMID + c] = fw[o * CMID + c] * g;

    for (int i = tid; i < NTAPS * CIN * CMID; i += 128) {
        int t   = i / (CIN * CMID);
        int rem = i - t * (CIN * CMID);
        int k   = rem / CMID;
        int cc  = rem - k * CMID;
        int oy = TAPY[t], ox = TAPX[t];
        float v = 0.f;
        if (t == 0) v += sw[0] * w1[cc * CIN + k];
        for (int d = 1; d <= 3; d++) {
            bool okY = (oy == 0) || (oy == d) || (oy == -d);
            bool okX = (ox == 0) || (ox == d) || (ox == -d);
            if (okY && okX) {
                int dy = oy / d + 1, dx = ox / d + 1;
                v += sw[d] * wj[d - 1][((cc * CIN + k) * 3 + dy) * 3 + dx];
            }
        }
        WG[i] = v;
    }
}

// ================= Kernel C: fused 25-tap conv + folded 1x1 epilogue =========
// smem (bytes): xs @0 (131328) [KHALF][TH][TWS], wsh @131328 (51200),
// As @182528 (2048), betas @184576 (64), fbs @184640 (128) => 184768
#define SMEM_XS_OFF   0
#define SMEM_WS_OFF   131328
#define SMEM_AS_OFF   182528
#define SMEM_BETA_OFF 184576
#define SMEM_FB_OFF   184640
#define SMEM_TOTAL    184768

__global__ void __launch_bounds__(NTHR, 1)
conv_kernel(const float* __restrict__ x, const float* __restrict__ fbias,
            float* __restrict__ out)
{
    extern __shared__ __align__(16) char smem[];
    float* xs    = (float*)(smem + SMEM_XS_OFF);     // [KHALF][TH][TWS]
    float* wsh   = (float*)(smem + SMEM_WS_OFF);     // [NTAPS][CIN][CMID]
    float* As    = (float*)(smem + SMEM_AS_OFF);     // [COUT][CMID]
    float* betas = (float*)(smem + SMEM_BETA_OFF);
    float* fbs   = (float*)(smem + SMEM_FB_OFF);

    const int b   = blockIdx.z;
    const int bh0 = blockIdx.y * TILE_H;
    const int bw0 = blockIdx.x * TILE_W;
    const int tid = threadIdx.x;

    for (int i = tid; i < NTAPS * CIN * CMID; i += NTHR) wsh[i] = WG[i];
    for (int i = tid; i < COUT * CMID; i += NTHR)       As[i]  = AG[b * COUT * CMID + i];
    if (tid < CMID) betas[tid] = betaG[b * CMID + tid];
    if (tid < COUT) fbs[tid]   = fbias[tid];

    const int w  = tid % TILE_W;    // 0..47
    const int rg = tid / TILE_W;    // 0..7 -> rows rg*4 .. rg*4+3

    ull acc[4][8];                  // [pixel-row][channel-pair]
#pragma unroll
    for (int p = 0; p < 4; p++)
#pragma unroll
        for (int cp = 0; cp < 8; cp++) acc[p][cp] = 0ULL;

    const float* xb = x + (size_t)b * CIN * HW;
    const int xbaseoff = (rg * 4 + 3) * TWS + (w + 3);

    for (int half = 0; half < 2; half++) {
        if (half) __syncthreads();           // compute done before overwrite
        // stage 16 channels (+halo) into smem
        for (int i = tid; i < KHALF * TH * TWS; i += NTHR) {
            int k   = i / (TH * TWS);
            int rem = i - k * (TH * TWS);
            int r   = rem / TWS;
            int cc  = rem - r * TWS;
            int gh = bh0 - 3 + r, gw = bw0 - 3 + cc;
            float v = 0.f;
            if ((unsigned)gh < Hdim && (unsigned)gw < Wdim)
                v = xb[(size_t)(half * KHALF + k) * HW + (size_t)gh * Wdim + gw];
            xs[i] = v;
        }
        __syncthreads();

#pragma unroll 1
        for (int t = 0; t < NTAPS; t++) {
            const float* xp = xs + xbaseoff + TAPY[t] * TWS + TAPX[t];
            const ull*   wp = (const ull*)(wsh + (t * CIN + half * KHALF) * CMID);
#pragma unroll 4
            for (int k = 0; k < KHALF; k++) {
                const float* xk = xp + k * (TH * TWS);
                float x0 = xk[0];
                float x1 = xk[TWS];
                float x2 = xk[2 * TWS];
                float x3 = xk[3 * TWS];
                ull xv0 = pack1(x0);
                ull xv1 = pack1(x1);
                ull xv2 = pack1(x2);
                ull xv3 = pack1(x3);
                const ull* wk = wp + k * 8;
#pragma unroll
                for (int cp = 0; cp < 8; cp++) {
                    ull wv = wk[cp];
                    fma2(acc[0][cp], xv0, wv);
                    fma2(acc[1][cp], xv1, wv);
                    fma2(acc[2][cp], xv2, wv);
                    fma2(acc[3][cp], xv3, wv);
                }
            }
        }
    }

    // T = acc + beta (vectorized)
    const ull* beta2 = (const ull*)betas;
#pragma unroll
    for (int p = 0; p < 4; p++)
#pragma unroll
        for (int cp = 0; cp < 8; cp++) add2(acc[p][cp], beta2[cp]);

    // folded per-batch 1x1: out[o] = fb[o] + sum_c A[b,o,c]*T[c]
    const ull* A2 = (const ull*)As;
    float* ob = out + (size_t)b * COUT * HW
                    + (size_t)(bh0 + rg * 4) * Wdim + (bw0 + w);
#pragma unroll 2
    for (int o = 0; o < COUT; o++) {
        float bias = fbs[o];
        const ull* Ao = A2 + o * 8;
#pragma unroll
        for (int p = 0; p < 4; p++) {
            ull s = 0ULL;
#pragma unroll
            for (int cp = 0; cp < 8; cp++) fma2(s, acc[p][cp], Ao[cp]);
            float2 f = unpack2(s);
            ob[(size_t)o * HW + (size_t)p * Wdim] = bias + f.x + f.y;
        }
    }
}

// ================= launch ====================================================
extern "C" void kernel_launch(void* const* d_in, const int* in_sizes, int n_in,
                              void* d_out, int out_size) {
    (void)in_sizes; (void)n_in; (void)out_size;
    const float* x     = (const float*)d_in[0];
    const float* w1    = (const float*)d_in[1];
    const float* b1    = (const float*)d_in[2];
    const float* w2    = (const float*)d_in[3];
    const float* b2    = (const float*)d_in[4];
    const float* w3    = (const float*)d_in[5];
    const float* b3    = (const float*)d_in[6];
    const float* w4    = (const float*)d_in[7];
    const float* b4    = (const float*)d_in[8];
    const float* w5    = (const float*)d_in[9];
    const float* b5    = (const float*)d_in[10];
    const float* gcn_w = (const float*)d_in[11];
    const float* gcn_b = (const float*)d_in[12];
    const float* attn  = (const float*)d_in[13];
    const float* fw    = (const float*)d_in[14];
    const float* fb    = (const float*)d_in[15];
    float* out = (float*)d_out;

    cudaFuncSetAttribute(conv_kernel,
                         cudaFuncAttributeMaxDynamicSharedMemorySize, SMEM_TOTAL);

    stats_kernel<<<B_ * CIN, 512>>>(x);
    prep_kernel<<<1, 128>>>(w1, b1, w2, b2, w3, b3, w4, b4, w5, b5,
                            gcn_w, gcn_b, attn, fw);
    dim3 grid(Wdim / TILE_W, Hdim / TILE_H, B_);   // 8 x 12 x 8 = 768 blocks
    conv_kernel<<<grid, NTHR, SMEM_TOTAL>>>(x, fb, out);
}

// round 8
// speedup vs baseline: 1.5018x; 1.0046x over previous
#include <cuda_runtime.h>

#define B_    8
#define CIN   32
#define CMID  16
#define COUT  32
#define Hdim  384
#define Wdim  384
#define HW    (Hdim * Wdim)
#define NTAPS 25
#define KHALF 16

#define TILE_H 32
#define TILE_W 48
#define TH (TILE_H + 6)   // 38
#define TWS (TILE_W + 6)  // 54
#define NTHR 384

typedef unsigned long long ull;

// ---------------- scratch (__device__ globals; no allocation) ----------------
// per (b,k): [0]=full sum, [1..6]=row sums (rows 0,1,2,H-3,H-2,H-1),
// [7..12]=col sums (same set), [13..48]=corner elems (6x6)
__device__ float statsG[B_ * CIN * 49];
__device__ float WG[NTAPS * CIN * CMID];   // combined softmax-weighted tap weights [t][k][c]
__device__ float betaG[B_ * CMID];         // per-(b,c) constant of T
__device__ float AG[B_ * COUT * CMID];     // folded epilogue weights fusion_w[o,c]*g[b,c]

__constant__ int TAPY[NTAPS] = {0, -1,-1,-1, 0, 0, 1, 1, 1,
                                   -2,-2,-2, 0, 0, 2, 2, 2,
                                   -3,-3,-3, 0, 0, 3, 3, 3};
__constant__ int TAPX[NTAPS] = {0, -1, 0, 1,-1, 1,-1, 0, 1,
                                   -2, 0, 2,-2, 2,-2, 0, 2,
                                   -3, 0, 3,-3, 3,-3, 0, 3};

// ---------------- f32x2 helpers (FFMA2 — PTX only) ---------------------------
__device__ __forceinline__ ull pack1(float a) {
    ull r; asm("mov.b64 %0, {%1,%1};" : "=l"(r) : "f"(a)); return r;
}
__device__ __forceinline__ void fma2(ull& d, ull a, ull b) {
    asm("fma.rn.f32x2 %0, %1, %2, %0;" : "+l"(d) : "l"(a), "l"(b));
}
__device__ __forceinline__ void add2(ull& d, ull a) {
    asm("add.rn.f32x2 %0, %0, %1;" : "+l"(d) : "l"(a));
}
__device__ __forceinline__ float2 unpack2(ull v) {
    float2 f; asm("mov.b64 {%0,%1}, %2;" : "=f"(f.x), "=f"(f.y) : "l"(v)); return f;
}

// ================= Kernel A: per-(b,k) plane statistics ======================
__global__ void __launch_bounds__(512)
stats_kernel(const float* __restrict__ x) {
    const int bk  = blockIdx.x;                 // b*32+k
    const float* p = x + (size_t)bk * HW;
    float* st = statsG + bk * 49;
    const int tid  = threadIdx.x;
    const int wid  = tid >> 5;
    const int lane = tid & 31;
    __shared__ float red[512];

    const int RI[6] = {0, 1, 2, Hdim - 3, Hdim - 2, Hdim - 1};

    // full sum: float4 loads, deterministic tree reduce
    const float4* p4 = (const float4*)p;
    float s = 0.f;
    for (int i = tid; i < HW / 4; i += 512) {
        float4 v = p4[i];
        s += (v.x + v.y) + (v.z + v.w);
    }
    red[tid] = s; __syncthreads();
    for (int d = 256; d > 0; d >>= 1) {
        if (tid < d) red[tid] += red[tid + d];
        __syncthreads();
    }
    if (tid == 0) st[0] = red[0];

    // 12 border sums: one warp each (warps 0..11), shfl reduce (deterministic)
    if (wid < 6) {                      // row sums
        float rs = 0.f;
        const float* row = p + RI[wid] * Wdim;
        for (int wv = lane; wv < Wdim; wv += 32) rs += row[wv];
        for (int d = 16; d > 0; d >>= 1)
            rs += __shfl_xor_sync(0xFFFFFFFF, rs, d);
        if (lane == 0) st[1 + wid] = rs;
    } else if (wid < 12) {              // col sums
        int j = wid - 6;
        float cs = 0.f;
        for (int h = lane; h < Hdim; h += 32) cs += p[h * Wdim + RI[j]];
        for (int d = 16; d > 0; d >>= 1)
            cs += __shfl_xor_sync(0xFFFFFFFF, cs, d);
        if (lane == 0) st[7 + j] = cs;
    } else if (wid == 14 && lane < 32) { // corners (36 elems -> lanes of warps 14/15)
        if (lane < 32) {
            int t = lane;
            if (t < 36) st[13 + t] = p[RI[t / 6] * Wdim + RI[t % 6]];
        }
    } else if (wid == 15 && lane < 4) {
        int t = 32 + lane;
        st[13 + t] = p[RI[t / 6] * Wdim + RI[t % 6]];
    }
}

// exact spatial sum of zero-padded shifted plane
__device__ __forceinline__ float rectsum(const float* st, int oy, int ox) {
    float s = st[0];
    int r0, r1, c0, c1;
    if (oy > 0)      { r0 = 0;      r1 = oy; }
    else if (oy < 0) { r0 = 6 + oy; r1 = 6;  }
    else             { r0 = 0;      r1 = 0;  }
    if (ox > 0)      { c0 = 0;      c1 = ox; }
    else if (ox < 0) { c0 = 6 + ox; c1 = 6;  }
    else             { c0 = 0;      c1 = 0;  }
    for (int i = r0; i < r1; i++) s -= st[1 + i];
    for (int j = c0; j < c1; j++) s -= st[7 + j];
    for (int i = r0; i < r1; i++)
        for (int j = c0; j < c1; j++) s += st[13 + i * 6 + j];
    return s;
}

// ================= Kernel B: tiny prep (softmax, g, beta, A, combined W) =====
__global__ void prep_kernel(
    const float* __restrict__ w1, const float* __restrict__ b1,
    const float* __restrict__ w2, const float* __restrict__ b2,
    const float* __restrict__ w3, const float* __restrict__ b3,
    const float* __restrict__ w4, const float* __restrict__ b4,
    const float* __restrict__ w5, const float* __restrict__ b5,
    const float* __restrict__ gcn_w, const float* __restrict__ gcn_b,
    const float* __restrict__ attn,
    const float* __restrict__ fw)
{
    __shared__ float mg[B_][CMID];
    __shared__ float sw[5];
    const int tid = threadIdx.x;   // 128 threads = B_*CMID

    if (tid == 0) {
        float mx = attn[0];
        for (int i = 1; i < 5; i++) mx = fmaxf(mx, attn[i]);
        float e[5], se = 0.f;
        for (int i = 0; i < 5; i++) { e[i] = expf(attn[i] - mx); se += e[i]; }
        for (int i = 0; i < 5; i++) sw[i] = e[i] / se;
    }
    __syncthreads();

    const int b = tid >> 4, c = tid & 15;
    const float inv = 1.f / (float)HW;
    const float* wj[3] = {w2, w3, w4};

    float f5 = b5[c];
    for (int k = 0; k < CIN; k++)
        f5 += w5[c * CIN + k] * statsG[(b * CIN + k) * 49] * inv;

    float nm0 = b1[c];
    for (int k = 0; k < CIN; k++)
        nm0 += w1[c * CIN + k] * statsG[(b * CIN + k) * 49] * inv;

    float nmd[3] = {b2[c], b3[c], b4[c]};
    for (int d = 1; d <= 3; d++) {
        float acc = 0.f;
        for (int k = 0; k < CIN; k++) {
            const float* st = &statsG[(b * CIN + k) * 49];
            for (int dy = 0; dy < 3; dy++)
                for (int dx = 0; dx < 3; dx++) {
                    float wv = wj[d - 1][((c * CIN + k) * 3 + dy) * 3 + dx];
                    acc += wv * rectsum(st, (dy - 1) * d, (dx - 1) * d);
                }
        }
        nmd[d - 1] += acc * inv;
    }

    mg[b][c] = (nm0 + nmd[0] + nmd[1] + nmd[2] + f5) * 0.2f;

    betaG[b * CMID + c] = sw[0] * b1[c] + sw[1] * b2[c] + sw[2] * b3[c]
                        + sw[3] * b4[c] + sw[4] * f5;
    __syncthreads();

    float g = gcn_b[c];
    for (int cp = 0; cp < CMID; cp++) g += mg[b][cp] * gcn_w[cp * CMID + c];
    for (int o = 0; o < COUT; o++)
        AG[(b * COUT + o) * CMID + c] = fw[o * CMID + c] * g;

    for (int i = tid; i < NTAPS * CIN * CMID; i += 128) {
        int t   = i / (CIN * CMID);
        int rem = i - t * (CIN * CMID);
        int k   = rem / CMID;
        int cc  = rem - k * CMID;
        int oy = TAPY[t], ox = TAPX[t];
        float v = 0.f;
        if (t == 0) v += sw[0] * w1[cc * CIN + k];
        for (int d = 1; d <= 3; d++) {
            bool okY = (oy == 0) || (oy == d) || (oy == -d);
            bool okX = (ox == 0) || (ox == d) || (ox == -d);
            if (okY && okX) {
                int dy = oy / d + 1, dx = ox / d + 1;
                v += sw[d] * wj[d - 1][((cc * CIN + k) * 3 + dy) * 3 + dx];
            }
        }
        WG[i] = v;
    }
}

// ================= Kernel C: fused 25-tap conv + folded 1x1 epilogue =========
// smem (bytes): xs @0 (131328) [KHALF][TH][TWS], wsh @131328 (51200),
// As @182528 (2048), betas @184576 (64), fbs @184640 (128) => 184768
#define SMEM_XS_OFF   0
#define SMEM_WS_OFF   131328
#define SMEM_AS_OFF   182528
#define SMEM_BETA_OFF 184576
#define SMEM_FB_OFF   184640
#define SMEM_TOTAL    184768

__global__ void __launch_bounds__(NTHR, 1)
conv_kernel(const float* __restrict__ x, const float* __restrict__ fbias,
            float* __restrict__ out)
{
    extern __shared__ __align__(16) char smem[];
    float* xs    = (float*)(smem + SMEM_XS_OFF);     // [KHALF][TH][TWS]
    float* wsh   = (float*)(smem + SMEM_WS_OFF);     // [NTAPS][CIN][CMID]
    float* As    = (float*)(smem + SMEM_AS_OFF);     // [COUT][CMID]
    float* betas = (float*)(smem + SMEM_BETA_OFF);
    float* fbs   = (float*)(smem + SMEM_FB_OFF);

    const int b   = blockIdx.z;
    const int bh0 = blockIdx.y * TILE_H;
    const int bw0 = blockIdx.x * TILE_W;
    const int tid = threadIdx.x;

    for (int i = tid; i < NTAPS * CIN * CMID; i += NTHR) wsh[i] = WG[i];
    for (int i = tid; i < COUT * CMID; i += NTHR)       As[i]  = AG[b * COUT * CMID + i];
    if (tid < CMID) betas[tid] = betaG[b * CMID + tid];
    if (tid < COUT) fbs[tid]   = fbias[tid];

    const int w  = tid % TILE_W;    // 0..47
    const int rg = tid / TILE_W;    // 0..7 -> rows rg*4 .. rg*4+3

    ull acc[4][8];                  // [pixel-row][channel-pair]
#pragma unroll
    for (int p = 0; p < 4; p++)
#pragma unroll
        for (int cp = 0; cp < 8; cp++) acc[p][cp] = 0ULL;

    const float* xb = x + (size_t)b * CIN * HW;
    const int xbaseoff = (rg * 4 + 3) * TWS + (w + 3);

    for (int half = 0; half < 2; half++) {
        if (half) __syncthreads();           // compute done before overwrite
        // stage 16 channels (+halo) into smem
        for (int i = tid; i < KHALF * TH * TWS; i += NTHR) {
            int k   = i / (TH * TWS);
            int rem = i - k * (TH * TWS);
            int r   = rem / TWS;
            int cc  = rem - r * TWS;
            int gh = bh0 - 3 + r, gw = bw0 - 3 + cc;
            float v = 0.f;
            if ((unsigned)gh < Hdim && (unsigned)gw < Wdim)
                v = xb[(size_t)(half * KHALF + k) * HW + (size_t)gh * Wdim + gw];
            xs[i] = v;
        }
        __syncthreads();

#pragma unroll 1
        for (int t = 0; t < NTAPS; t++) {
            const float* xp = xs + xbaseoff + TAPY[t] * TWS + TAPX[t];
            const ull*   wp = (const ull*)(wsh + (t * CIN + half * KHALF) * CMID);
#pragma unroll 4
            for (int k = 0; k < KHALF; k++) {
                const float* xk = xp + k * (TH * TWS);
                float x0 = xk[0];
                float x1 = xk[TWS];
                float x2 = xk[2 * TWS];
                float x3 = xk[3 * TWS];
                ull xv0 = pack1(x0);
                ull xv1 = pack1(x1);
                ull xv2 = pack1(x2);
                ull xv3 = pack1(x3);
                const ull* wk = wp + k * 8;
#pragma unroll
                for (int cp = 0; cp < 8; cp++) {
                    ull wv = wk[cp];
                    fma2(acc[0][cp], xv0, wv);
                    fma2(acc[1][cp], xv1, wv);
                    fma2(acc[2][cp], xv2, wv);
                    fma2(acc[3][cp], xv3, wv);
                }
            }
        }
    }

    // T = acc + beta (vectorized)
    const ull* beta2 = (const ull*)betas;
#pragma unroll
    for (int p = 0; p < 4; p++)
#pragma unroll
        for (int cp = 0; cp < 8; cp++) add2(acc[p][cp], beta2[cp]);

    // folded per-batch 1x1: out[o] = fb[o] + sum_c A[b,o,c]*T[c]
    const ull* A2 = (const ull*)As;
    float* ob = out + (size_t)b * COUT * HW
                    + (size_t)(bh0 + rg * 4) * Wdim + (bw0 + w);
#pragma unroll 2
    for (int o = 0; o < COUT; o++) {
        float bias = fbs[o];
        const ull* Ao = A2 + o * 8;
#pragma unroll
        for (int p = 0; p < 4; p++) {
            ull s = 0ULL;
#pragma unroll
            for (int cp = 0; cp < 8; cp++) fma2(s, acc[p][cp], Ao[cp]);
            float2 f = unpack2(s);
            ob[(size_t)o * HW + (size_t)p * Wdim] = bias + f.x + f.y;
        }
    }
}

// ================= launch ====================================================
extern "C" void kernel_launch(void* const* d_in, const int* in_sizes, int n_in,
                              void* d_out, int out_size) {
    (void)in_sizes; (void)n_in; (void)out_size;
    const float* x     = (const float*)d_in[0];
    const float* w1    = (const float*)d_in[1];
    const float* b1    = (const float*)d_in[2];
    const float* w2    = (const float*)d_in[3];
    const float* b2    = (const float*)d_in[4];
    const float* w3    = (const float*)d_in[5];
    const float* b3    = (const float*)d_in[6];
    const float* w4    = (const float*)d_in[7];
    const float* b4    = (const float*)d_in[8];
    const float* w5    = (const float*)d_in[9];
    const float* b5    = (const float*)d_in[10];
    const float* gcn_w = (const float*)d_in[11];
    const float* gcn_b = (const float*)d_in[12];
    const float* attn  = (const float*)d_in[13];
    const float* fw    = (const float*)d_in[14];
    const float* fb    = (const float*)d_in[15];
    float* out = (float*)d_out;

    cudaFuncSetAttribute(conv_kernel,
                         cudaFuncAttributeMaxDynamicSharedMemorySize, SMEM_TOTAL);

    stats_kernel<<<B_ * CIN, 512>>>(x);
    prep_kernel<<<1, 128>>>(w1, b1, w2, b2, w3, b3, w4, b4, w5, b5,
                            gcn_w, gcn_b, attn, fw);
    dim3 grid(Wdim / TILE_W, Hdim / TILE_H, B_);   // 8 x 12 x 8 = 768 blocks
    conv_kernel<<<grid, NTHR, SMEM_TOTAL>>>(x, fb, out);
}

// round 10
// speedup vs baseline: 2.4332x; 1.6202x over previous
#include <cuda_runtime.h>
#include <cuda_fp16.h>
#include <cstdint>

#define B_    8
#define CIN   32
#define CMID  16
#define COUT  32
#define Hdim  384
#define Wdim  384
#define HW    (Hdim * Wdim)
#define NTAPS 25
#define NCHUNK 50            // 25 taps x 2 channel-halves, k=16 each

// conv tiling: 16x16 pixels per CTA, 256 threads (8 warps, 32 px/warp)
#define TPX 16
#define WPOS 22              // 16 + 6 halo
#define NPOS (WPOS * WPOS)   // 484
#define PITCH 18             // words per pixel (16 data + 2 pad; conflict-free)

// smem layout (bytes)
#define SM_XSW  0
#define SM_BHI  34848        // 484*18*4
#define SM_BLO  60448
#define SM_AS   86048
#define SM_CONS 88096
#define SMEM_TOTAL 88224

// ---------------- device scratch (static; no allocation) ---------------------
__device__ float statsG[B_ * CIN * 49];
__device__ float WG[NTAPS * CIN * CMID];       // combined tap weights [t][k][c]
__device__ float betaG[B_ * CMID];
__device__ float AG[B_ * COUT * CMID];
__device__ float constG[B_ * COUT];
__device__ unsigned short xpkG[(size_t)B_ * HW * CIN];   // NHWC fp16
__device__ unsigned WbhiG[NCHUNK * 128];       // B frag words [chunk][n][kw] (hi)
__device__ unsigned WbloG[NCHUNK * 128];       // (lo)

__constant__ int TAPY[NTAPS] = {0, -1,-1,-1, 0, 0, 1, 1, 1,
                                   -2,-2,-2, 0, 0, 2, 2, 2,
                                   -3,-3,-3, 0, 0, 3, 3, 3};
__constant__ int TAPX[NTAPS] = {0, -1, 0, 1,-1, 1,-1, 0, 1,
                                   -2, 0, 2,-2, 2,-2, 0, 2,
                                   -3, 0, 3,-3, 3,-3, 0, 3};

// ---------------- helpers ----------------------------------------------------
__device__ __forceinline__ unsigned f16x2pack(float hi, float lo) {
    unsigned r;
    asm("cvt.rn.f16x2.f32 %0, %1, %2;" : "=r"(r) : "f"(hi), "f"(lo));
    return r;   // lower half = lo, upper half = hi
}
__device__ __forceinline__ void mma16816(float* d,
        unsigned a0, unsigned a1, unsigned a2, unsigned a3,
        unsigned b0, unsigned b1) {
    asm volatile("mma.sync.aligned.m16n8k16.row.col.f32.f16.f16.f32 "
        "{%0,%1,%2,%3}, {%4,%5,%6,%7}, {%8,%9}, {%0,%1,%2,%3};"
        : "+f"(d[0]), "+f"(d[1]), "+f"(d[2]), "+f"(d[3])
        : "r"(a0), "r"(a1), "r"(a2), "r"(a3), "r"(b0), "r"(b1));
}

// ================= Kernel A: per-(b,k) plane statistics (exact fp32) =========
__global__ void __launch_bounds__(512)
stats_kernel(const float* __restrict__ x) {
    const int bk  = blockIdx.x;
    const float* p = x + (size_t)bk * HW;
    float* st = statsG + bk * 49;
    const int tid  = threadIdx.x;
    const int wid  = tid >> 5;
    const int lane = tid & 31;
    __shared__ float red[512];
    const int RI[6] = {0, 1, 2, Hdim - 3, Hdim - 2, Hdim - 1};

    const float4* p4 = (const float4*)p;
    float s = 0.f;
    for (int i = tid; i < HW / 4; i += 512) {
        float4 v = p4[i];
        s += (v.x + v.y) + (v.z + v.w);
    }
    red[tid] = s; __syncthreads();
    for (int d = 256; d > 0; d >>= 1) {
        if (tid < d) red[tid] += red[tid + d];
        __syncthreads();
    }
    if (tid == 0) st[0] = red[0];

    if (wid < 6) {
        float rs = 0.f;
        const float* row = p + RI[wid] * Wdim;
        for (int wv = lane; wv < Wdim; wv += 32) rs += row[wv];
        for (int d = 16; d > 0; d >>= 1) rs += __shfl_xor_sync(0xFFFFFFFF, rs, d);
        if (lane == 0) st[1 + wid] = rs;
    } else if (wid < 12) {
        int j = wid - 6;
        float cs = 0.f;
        for (int h = lane; h < Hdim; h += 32) cs += p[h * Wdim + RI[j]];
        for (int d = 16; d > 0; d >>= 1) cs += __shfl_xor_sync(0xFFFFFFFF, cs, d);
        if (lane == 0) st[7 + j] = cs;
    } else if (wid == 14) {
        if (lane < 36) st[13 + lane] = p[RI[lane / 6] * Wdim + RI[lane % 6]];
    }
}

__device__ __forceinline__ float rectsum(const float* st, int oy, int ox) {
    float s = st[0];
    int r0, r1, c0, c1;
    if (oy > 0)      { r0 = 0;      r1 = oy; }
    else if (oy < 0) { r0 = 6 + oy; r1 = 6;  }
    else             { r0 = 0;      r1 = 0;  }
    if (ox > 0)      { c0 = 0;      c1 = ox; }
    else if (ox < 0) { c0 = 6 + ox; c1 = 6;  }
    else             { c0 = 0;      c1 = 0;  }
    for (int i = r0; i < r1; i++) s -= st[1 + i];
    for (int j = c0; j < c1; j++) s -= st[7 + j];
    for (int i = r0; i < r1; i++)
        for (int j = c0; j < c1; j++) s += st[13 + i * 6 + j];
    return s;
}

// ================= Kernel B: prep (softmax, g, beta, A-fold, WG, const) ======
__global__ void prep_kernel(
    const float* __restrict__ w1, const float* __restrict__ b1,
    const float* __restrict__ w2, const float* __restrict__ b2,
    const float* __restrict__ w3, const float* __restrict__ b3,
    const float* __restrict__ w4, const float* __restrict__ b4,
    const float* __restrict__ w5, const float* __restrict__ b5,
    const float* __restrict__ gcn_w, const float* __restrict__ gcn_b,
    const float* __restrict__ attn,
    const float* __restrict__ fw, const float* __restrict__ fb)
{
    __shared__ float mg[B_][CMID];
    __shared__ float sw[5];
    const int tid = threadIdx.x;   // 128

    if (tid == 0) {
        float mx = attn[0];
        for (int i = 1; i < 5; i++) mx = fmaxf(mx, attn[i]);
        float e[5], se = 0.f;
        for (int i = 0; i < 5; i++) { e[i] = expf(attn[i] - mx); se += e[i]; }
        for (int i = 0; i < 5; i++) sw[i] = e[i] / se;
    }
    __syncthreads();

    const int b = tid >> 4, c = tid & 15;
    const float inv = 1.f / (float)HW;
    const float* wj[3] = {w2, w3, w4};

    float f5 = b5[c];
    for (int k = 0; k < CIN; k++)
        f5 += w5[c * CIN + k] * statsG[(b * CIN + k) * 49] * inv;

    float nm0 = b1[c];
    for (int k = 0; k < CIN; k++)
        nm0 += w1[c * CIN + k] * statsG[(b * CIN + k) * 49] * inv;

    float nmd[3] = {b2[c], b3[c], b4[c]};
    for (int d = 1; d <= 3; d++) {
        float acc = 0.f;
        for (int k = 0; k < CIN; k++) {
            const float* st = &statsG[(b * CIN + k) * 49];
            for (int dy = 0; dy < 3; dy++)
                for (int dx = 0; dx < 3; dx++) {
                    float wv = wj[d - 1][((c * CIN + k) * 3 + dy) * 3 + dx];
                    acc += wv * rectsum(st, (dy - 1) * d, (dx - 1) * d);
                }
        }
        nmd[d - 1] += acc * inv;
    }

    mg[b][c] = (nm0 + nmd[0] + nmd[1] + nmd[2] + f5) * 0.2f;
    betaG[b * CMID + c] = sw[0] * b1[c] + sw[1] * b2[c] + sw[2] * b3[c]
                        + sw[3] * b4[c] + sw[4] * f5;
    __syncthreads();

    float g = gcn_b[c];
    for (int cp = 0; cp < CMID; cp++) g += mg[b][cp] * gcn_w[cp * CMID + c];
    for (int o = 0; o < COUT; o++)
        AG[(b * COUT + o) * CMID + c] = fw[o * CMID + c] * g;

    for (int i = tid; i < NTAPS * CIN * CMID; i += 128) {
        int t   = i / (CIN * CMID);
        int rem = i - t * (CIN * CMID);
        int k   = rem / CMID;
        int cc  = rem - k * CMID;
        int oy = TAPY[t], ox = TAPX[t];
        float v = 0.f;
        if (t == 0) v += sw[0] * w1[cc * CIN + k];
        for (int d = 1; d <= 3; d++) {
            bool okY = (oy == 0) || (oy == d) || (oy == -d);
            bool okX = (ox == 0) || (ox == d) || (ox == -d);
            if (okY && okX) {
                int dy = oy / d + 1, dx = ox / d + 1;
                v += sw[d] * wj[d - 1][((cc * CIN + k) * 3 + dy) * 3 + dx];
            }
        }
        WG[i] = v;
    }
    __syncthreads();

    // constG[b][o] = fb[o] + sum_c AG[b,o,c]*beta[b,c]
    for (int i = tid; i < B_ * COUT; i += 128) {
        int bb = i >> 5, o = i & 31;
        float v = fb[o];
        for (int cc2 = 0; cc2 < CMID; cc2++)
            v += AG[(bb * COUT + o) * CMID + cc2] * betaG[bb * CMID + cc2];
        constG[i] = v;
    }
}

// ================= Kernel B2: build hi/lo fp16 B fragment words ==============
// word layout: [chunk][n][kw], word packs k = 2*kw (lower), 2*kw+1 (upper)
__global__ void __launch_bounds__(256)
prep2_kernel() {
    for (int i = threadIdx.x; i < NCHUNK * 128; i += 256) {
        int chunk = i >> 7;
        int rem   = i & 127;
        int n     = rem >> 3;
        int kw    = rem & 7;
        int tap   = chunk >> 1;
        int half  = chunk & 1;
        int kin   = half * 16 + 2 * kw;
        float v0 = WG[(tap * CIN + kin) * CMID + n] * 1024.f;
        float v1 = WG[(tap * CIN + kin + 1) * CMID + n] * 1024.f;
        __half h0 = __float2half_rn(v0);
        __half h1 = __float2half_rn(v1);
        __half l0 = __float2half_rn(v0 - __half2float(h0));
        __half l1 = __float2half_rn(v1 - __half2float(h1));
        WbhiG[i] = (unsigned)__half_as_ushort(h0)
                 | ((unsigned)__half_as_ushort(h1) << 16);
        WbloG[i] = (unsigned)__half_as_ushort(l0)
                 | ((unsigned)__half_as_ushort(l1) << 16);
    }
}

// ================= Kernel P: fp32 NCHW -> fp16 NHWC ==========================
__global__ void __launch_bounds__(256)
presplit_kernel(const float* __restrict__ x) {
    const int b = blockIdx.z, h = blockIdx.y, wx = blockIdx.x;
    const int tid = threadIdx.x;
    const int kq = tid & 7, wq = tid >> 3;
    const int k0 = kq * 4, w0 = wx * 128 + wq * 4;

    float v[4][4];
    const float* xp = x + (size_t)b * CIN * HW + (size_t)h * Wdim + w0;
#pragma unroll
    for (int j = 0; j < 4; j++) {
        float4 f = *(const float4*)(xp + (size_t)(k0 + j) * HW);
        v[j][0] = f.x; v[j][1] = f.y; v[j][2] = f.z; v[j][3] = f.w;
    }
    unsigned short* dst = xpkG + ((size_t)b * HW + (size_t)h * Wdim + w0) * CIN + k0;
#pragma unroll
    for (int i = 0; i < 4; i++) {
        unsigned r0 = f16x2pack(v[1][i], v[0][i]);   // lower = even channel
        unsigned r1 = f16x2pack(v[3][i], v[2][i]);
        *(uint2*)(dst + (size_t)i * CIN) = make_uint2(r0, r1);
    }
}

// ================= Kernel C: HMMA implicit-GEMM conv + fp32 epilogue =========
__global__ void __launch_bounds__(256)
conv_kernel(float* __restrict__ out) {
    extern __shared__ __align__(16) char smem[];
    float*    xsw = (float*)(smem + SM_XSW);     // window [484][18] words
    unsigned* bhi = (unsigned*)(smem + SM_BHI);  // [50][16][8]
    unsigned* blo = (unsigned*)(smem + SM_BLO);
    float*    As  = (float*)(smem + SM_AS);      // [32][16] (prescaled /1024)
    float*    cons = (float*)(smem + SM_CONS);   // [32]

    const int b  = blockIdx.z;
    const int tY = blockIdx.y, tX = blockIdx.x;
    const int tid  = threadIdx.x;
    const int w    = tid >> 5;        // warp 0..7
    const int lane = tid & 31;
    const int g    = lane >> 2;       // 0..7
    const int tg   = lane & 3;        // 0..3

    // ---- stage B fragments + epilogue constants
    {
        const uint4* sH = (const uint4*)WbhiG;
        const uint4* sL = (const uint4*)WbloG;
        uint4* dH = (uint4*)bhi;
        uint4* dL = (uint4*)blo;
        for (int i = tid; i < NCHUNK * 128 / 4; i += 256) { dH[i] = sH[i]; dL[i] = sL[i]; }
        for (int i = tid; i < COUT * CMID; i += 256)
            As[i] = AG[b * COUT * CMID + i] * (1.f / 1024.f);
        if (tid < COUT) cons[tid] = constG[b * COUT + tid];
    }

    // ---- stage x window (22x22 px, 32ch fp16, pad-18 pitch)
    {
        const unsigned short* xb = xpkG + (size_t)b * HW * CIN;
        const int gh0 = tY * TPX - 3, gw0 = tX * TPX - 3;
        for (int idx = tid; idx < NPOS * 4; idx += 256) {
            int pos = idx >> 2, c = idx & 3;
            int r = pos / WPOS, cc = pos - r * WPOS;
            int gh = gh0 + r, gw = gw0 + cc;
            uint4 v = make_uint4(0, 0, 0, 0);
            if ((unsigned)gh < Hdim && (unsigned)gw < Wdim)
                v = *(const uint4*)(xb + ((size_t)gh * Wdim + gw) * CIN + c * 8);
            uint2* d = (uint2*)(xsw + pos * PITCH + c * 4);  // 8B aligned
            d[0] = make_uint2(v.x, v.y);
            d[1] = make_uint2(v.z, v.w);
        }
    }
    __syncthreads();

    // ---- mainloop: 50 k-chunks, per warp 2 m16 tiles x 2 n8 tiles, hi+lo
    float d[2][2][4];
#pragma unroll
    for (int mt = 0; mt < 2; mt++)
#pragma unroll
        for (int nt = 0; nt < 2; nt++)
#pragma unroll
            for (int q = 0; q < 4; q++) d[mt][nt][q] = 0.f;

    // a0 pixel: (py = 2w+mt, px = g); a1: px = g+8
    const int abase = ((2 * w + 3) * WPOS + (g + 3)) * PITCH + tg;

#pragma unroll 2
    for (int chunk = 0; chunk < NCHUNK; chunk++) {
        const int tap  = chunk >> 1;
        const int half = chunk & 1;
        const int woff = (TAPY[tap] * WPOS + TAPX[tap]) * PITCH + half * 8;

        // B fragments (shared across mt)
        const int bw = chunk * 128 + g * 8 + tg;
        unsigned bh0[2], bh1[2], bl0[2], bl1[2];
#pragma unroll
        for (int nt = 0; nt < 2; nt++) {
            bh0[nt] = bhi[bw + nt * 64];
            bh1[nt] = bhi[bw + nt * 64 + 4];
            bl0[nt] = blo[bw + nt * 64];
            bl1[nt] = blo[bw + nt * 64 + 4];
        }

#pragma unroll
        for (int mt = 0; mt < 2; mt++) {
            const float* ap = xsw + abase + mt * (WPOS * PITCH) + woff;
            unsigned a0 = __float_as_uint(ap[0]);
            unsigned a1 = __float_as_uint(ap[8 * PITCH]);
            unsigned a2 = __float_as_uint(ap[4]);
            unsigned a3 = __float_as_uint(ap[8 * PITCH + 4]);
#pragma unroll
            for (int nt = 0; nt < 2; nt++) {
                mma16816(d[mt][nt], a0, a1, a2, a3, bh0[nt], bh1[nt]);
                mma16816(d[mt][nt], a0, a1, a2, a3, bl0[nt], bl1[nt]);
            }
        }
    }

    // ---- write T to smem (reuse window region), pitch 17 to spread banks
    __syncthreads();
    float* T = xsw;   // [256][17]
#pragma unroll
    for (int mt = 0; mt < 2; mt++) {
        int p0 = 32 * w + 16 * mt + g;
#pragma unroll
        for (int nt = 0; nt < 2; nt++) {
            int c0 = 8 * nt + 2 * tg;
            T[p0 * 17 + c0]           = d[mt][nt][0];
            T[p0 * 17 + c0 + 1]       = d[mt][nt][1];
            T[(p0 + 8) * 17 + c0]     = d[mt][nt][2];
            T[(p0 + 8) * 17 + c0 + 1] = d[mt][nt][3];
        }
    }
    __syncthreads();

    // ---- fp32 epilogue: out[o] = cons[o] + sum_c As[o,c]*T[p,c]
    {
        const int p = tid;
        float Tl[CMID];
#pragma unroll
        for (int c = 0; c < CMID; c++) Tl[c] = T[p * 17 + c];
        const int gy = tY * TPX + (p >> 4), gx = tX * TPX + (p & 15);
        float* ob = out + (size_t)b * COUT * HW + (size_t)gy * Wdim + gx;
#pragma unroll 4
        for (int o = 0; o < COUT; o++) {
            float acc = cons[o];
            const float* Ao = As + o * CMID;
#pragma unroll
            for (int c = 0; c < CMID; c++) acc = fmaf(Ao[c], Tl[c], acc);
            ob[(size_t)o * HW] = acc;
        }
    }
}

// ================= launch ====================================================
extern "C" void kernel_launch(void* const* d_in, const int* in_sizes, int n_in,
                              void* d_out, int out_size) {
    (void)in_sizes; (void)n_in; (void)out_size;
    const float* x     = (const float*)d_in[0];
    const float* w1    = (const float*)d_in[1];
    const float* b1    = (const float*)d_in[2];
    const float* w2    = (const float*)d_in[3];
    const float* b2    = (const float*)d_in[4];
    const float* w3    = (const float*)d_in[5];
    const float* b3    = (const float*)d_in[6];
    const float* w4    = (const float*)d_in[7];
    const float* b4    = (const float*)d_in[8];
    const float* w5    = (const float*)d_in[9];
    const float* b5    = (const float*)d_in[10];
    const float* gcn_w = (const float*)d_in[11];
    const float* gcn_b = (const float*)d_in[12];
    const float* attn  = (const float*)d_in[13];
    const float* fw    = (const float*)d_in[14];
    const float* fb    = (const float*)d_in[15];
    float* out = (float*)d_out;

    cudaFuncSetAttribute(conv_kernel,
                         cudaFuncAttributeMaxDynamicSharedMemorySize, SMEM_TOTAL);

    presplit_kernel<<<dim3(3, Hdim, B_), 256>>>(x);
    stats_kernel<<<B_ * CIN, 512>>>(x);
    prep_kernel<<<1, 128>>>(w1, b1, w2, b2, w3, b3, w4, b4, w5, b5,
                            gcn_w, gcn_b, attn, fw, fb);
    prep2_kernel<<<1, 256>>>();
    conv_kernel<<<dim3(Wdim / TPX, Hdim / TPX, B_), 256, SMEM_TOTAL>>>(out);
}

// round 14
// speedup vs baseline: 3.2364x; 1.3301x over previous
#include <cuda_runtime.h>
#include <cuda_fp16.h>
#include <cstdint>

#define B_    8
#define CIN   32
#define CMID  16
#define COUT  32
#define Hdim  384
#define Wdim  384
#define HW    (Hdim * Wdim)
#define NTAPS 25
#define NCHUNK 50            // 25 taps x 2 channel-halves (k=16 each)

// conv tiling: 16x16 pixels per CTA, 256 threads (8 warps)
#define TPX 16
#define WPOS 22              // 16 + 6 halo
#define NPOS (WPOS * WPOS)   // 484
#define PITCH 24             // words per pixel (16 data + 8 pad)

// smem layout (bytes)
#define SM_XSW  0                        // 484*24*4 = 46464
#define SM_BF   46464                    // 50*128*4 = 25600
#define SM_AS   72064                    // 2048
#define SM_CONS 74112                    // 128
#define SMEM_TOTAL 74240

// ---------------- device scratch (static; no allocation) ---------------------
__device__ float statsG[B_ * CIN * 49];
__device__ float WG[NTAPS * CIN * CMID];       // combined tap weights [t][k][c]
__device__ float betaG[B_ * CMID];
__device__ float AG[B_ * COUT * CMID];
__device__ float constG[B_ * COUT];
__device__ unsigned short xpkG[(size_t)B_ * HW * CIN];   // NHWC fp16, k-interleaved
__device__ unsigned WbG[NCHUNK * 128];         // B frag words [chunk][n][jpair]

__constant__ int TAPY[NTAPS] = {0, -1,-1,-1, 0, 0, 1, 1, 1,
                                   -2,-2,-2, 0, 0, 2, 2, 2,
                                   -3,-3,-3, 0, 0, 3, 3, 3};
__constant__ int TAPX[NTAPS] = {0, -1, 0, 1,-1, 1,-1, 0, 1,
                                   -2, 0, 2,-2, 2,-2, 0, 2,
                                   -3, 0, 3,-3, 3,-3, 0, 3};

// compile-time tap tables as constexpr functions (fold to immediates under
// full unroll). Ring decomposition: p=(t-1)&7, d=(t+7)/8.
//   rows: {-d,-d,-d, 0,0, d,d,d}  (3/2/3)
//   cols: {-d, 0, d, -d, d, -d, 0, d}
// Verified entry-by-entry against TAPY/TAPX for all t in [0,24].
__host__ __device__ constexpr int tap_d(int t) { return (t + 7) / 8; }
__host__ __device__ constexpr int tapy_c(int t) {
    return (t == 0) ? 0
         : ((((t - 1) & 7) < 3) ? -tap_d(t)
          : (((t - 1) & 7) < 5) ? 0 : tap_d(t));
}
__host__ __device__ constexpr int tapx_c(int t) {
    return (t == 0) ? 0
         : ((((t - 1) & 7) == 0 || ((t - 1) & 7) == 3 || ((t - 1) & 7) == 5)
                ? -tap_d(t)
          : (((t - 1) & 7) == 1 || ((t - 1) & 7) == 6) ? 0 : tap_d(t));
}

// ---------------- helpers ----------------------------------------------------
__device__ __forceinline__ unsigned f16x2pack(float hi, float lo) {
    unsigned r;
    asm("cvt.rn.f16x2.f32 %0, %1, %2;" : "=r"(r) : "f"(hi), "f"(lo));
    return r;   // lower half = lo, upper half = hi
}
__device__ __forceinline__ void mma16816(float* d,
        unsigned a0, unsigned a1, unsigned a2, unsigned a3,
        unsigned b0, unsigned b1) {
    asm volatile("mma.sync.aligned.m16n8k16.row.col.f32.f16.f16.f32 "
        "{%0,%1,%2,%3}, {%4,%5,%6,%7}, {%8,%9}, {%0,%1,%2,%3};"
        : "+f"(d[0]), "+f"(d[1]), "+f"(d[2]), "+f"(d[3])
        : "r"(a0), "r"(a1), "r"(a2), "r"(a3), "r"(b0), "r"(b1));
}

// ================= Kernel A: per-(b,k) plane statistics (exact fp32) =========
__global__ void __launch_bounds__(512)
stats_kernel(const float* __restrict__ x) {
    const int bk  = blockIdx.x;
    const float* p = x + (size_t)bk * HW;
    float* st = statsG + bk * 49;
    const int tid  = threadIdx.x;
    const int wid  = tid >> 5;
    const int lane = tid & 31;
    __shared__ float red[512];
    const int RI[6] = {0, 1, 2, Hdim - 3, Hdim - 2, Hdim - 1};

    const float4* p4 = (const float4*)p;
    float s = 0.f;
    for (int i = tid; i < HW / 4; i += 512) {
        float4 v = p4[i];
        s += (v.x + v.y) + (v.z + v.w);
    }
    red[tid] = s; __syncthreads();
    for (int d = 256; d > 0; d >>= 1) {
        if (tid < d) red[tid] += red[tid + d];
        __syncthreads();
    }
    if (tid == 0) st[0] = red[0];

    if (wid < 6) {
        float rs = 0.f;
        const float* row = p + RI[wid] * Wdim;
        for (int wv = lane; wv < Wdim; wv += 32) rs += row[wv];
        for (int d = 16; d > 0; d >>= 1) rs += __shfl_xor_sync(0xFFFFFFFF, rs, d);
        if (lane == 0) st[1 + wid] = rs;
    } else if (wid < 12) {
        int j = wid - 6;
        float cs = 0.f;
        for (int h = lane; h < Hdim; h += 32) cs += p[h * Wdim + RI[j]];
        for (int d = 16; d > 0; d >>= 1) cs += __shfl_xor_sync(0xFFFFFFFF, cs, d);
        if (lane == 0) st[7 + j] = cs;
    } else if (wid == 14) {
        if (lane < 36) st[13 + lane] = p[RI[lane / 6] * Wdim + RI[lane % 6]];
    }
}

__device__ __forceinline__ float rectsum(const float* st, int oy, int ox) {
    float s = st[0];
    int r0, r1, c0, c1;
    if (oy > 0)      { r0 = 0;      r1 = oy; }
    else if (oy < 0) { r0 = 6 + oy; r1 = 6;  }
    else             { r0 = 0;      r1 = 0;  }
    if (ox > 0)      { c0 = 0;      c1 = ox; }
    else if (ox < 0) { c0 = 6 + ox; c1 = 6;  }
    else             { c0 = 0;      c1 = 0;  }
    for (int i = r0; i < r1; i++) s -= st[1 + i];
    for (int j = c0; j < c1; j++) s -= st[7 + j];
    for (int i = r0; i < r1; i++)
        for (int j = c0; j < c1; j++) s += st[13 + i * 6 + j];
    return s;
}

// ========== Kernel B: prep (softmax, g, beta, A-fold, WG, const, B-frags) ====
__global__ void prep_kernel(
    const float* __restrict__ w1, const float* __restrict__ b1,
    const float* __restrict__ w2, const float* __restrict__ b2,
    const float* __restrict__ w3, const float* __restrict__ b3,
    const float* __restrict__ w4, const float* __restrict__ b4,
    const float* __restrict__ w5, const float* __restrict__ b5,
    const float* __restrict__ gcn_w, const float* __restrict__ gcn_b,
    const float* __restrict__ attn,
    const float* __restrict__ fw, const float* __restrict__ fb)
{
    __shared__ float mg[B_][CMID];
    __shared__ float sw[5];
    const int tid = threadIdx.x;   // 128

    if (tid == 0) {
        float mx = attn[0];
        for (int i = 1; i < 5; i++) mx = fmaxf(mx, attn[i]);
        float e[5], se = 0.f;
        for (int i = 0; i < 5; i++) { e[i] = expf(attn[i] - mx); se += e[i]; }
        for (int i = 0; i < 5; i++) sw[i] = e[i] / se;
    }
    __syncthreads();

    const int b = tid >> 4, c = tid & 15;
    const float inv = 1.f / (float)HW;
    const float* wj[3] = {w2, w3, w4};

    float f5 = b5[c];
    for (int k = 0; k < CIN; k++)
        f5 += w5[c * CIN + k] * statsG[(b * CIN + k) * 49] * inv;

    float nm0 = b1[c];
    for (int k = 0; k < CIN; k++)
        nm0 += w1[c * CIN + k] * statsG[(b * CIN + k) * 49] * inv;

    float nmd[3] = {b2[c], b3[c], b4[c]};
    for (int d = 1; d <= 3; d++) {
        float acc = 0.f;
        for (int k = 0; k < CIN; k++) {
            const float* st = &statsG[(b * CIN + k) * 49];
            for (int dy = 0; dy < 3; dy++)
                for (int dx = 0; dx < 3; dx++) {
                    float wv = wj[d - 1][((c * CIN + k) * 3 + dy) * 3 + dx];
                    acc += wv * rectsum(st, (dy - 1) * d, (dx - 1) * d);
                }
        }
        nmd[d - 1] += acc * inv;
    }

    mg[b][c] = (nm0 + nmd[0] + nmd[1] + nmd[2] + f5) * 0.2f;
    betaG[b * CMID + c] = sw[0] * b1[c] + sw[1] * b2[c] + sw[2] * b3[c]
                        + sw[3] * b4[c] + sw[4] * f5;
    __syncthreads();

    float g = gcn_b[c];
    for (int cp = 0; cp < CMID; cp++) g += mg[b][cp] * gcn_w[cp * CMID + c];
    for (int o = 0; o < COUT; o++)
        AG[(b * COUT + o) * CMID + c] = fw[o * CMID + c] * g;

    for (int i = tid; i < NTAPS * CIN * CMID; i += 128) {
        int t   = i / (CIN * CMID);
        int rem = i - t * (CIN * CMID);
        int k   = rem / CMID;
        int cc  = rem - k * CMID;
        int oy = TAPY[t], ox = TAPX[t];
        float v = 0.f;
        if (t == 0) v += sw[0] * w1[cc * CIN + k];
        for (int d = 1; d <= 3; d++) {
            bool okY = (oy == 0) || (oy == d) || (oy == -d);
            bool okX = (ox == 0) || (ox == d) || (ox == -d);
            if (okY && okX) {
                int dy = oy / d + 1, dx = ox / d + 1;
                v += sw[d] * wj[d - 1][((cc * CIN + k) * 3 + dy) * 3 + dx];
            }
        }
        WG[i] = v;
    }
    __syncthreads();

    // constG[b][o] = fb[o] + sum_c AG[b,o,c]*beta[b,c]
    for (int i = tid; i < B_ * COUT; i += 128) {
        int bb = i >> 5, o = i & 31;
        float v = fb[o];
        for (int cc2 = 0; cc2 < CMID; cc2++)
            v += AG[(bb * COUT + o) * CMID + cc2] * betaG[bb * CMID + cc2];
        constG[i] = v;
    }

    // B fragment words (hi only, x1024), interleaved pair layout:
    // [chunk][n][j]: j even -> k=(j,j+1); j odd -> k=(j-1+8, j+8)
    for (int i = tid; i < NCHUNK * 128; i += 128) {
        int chunk = i >> 7, rem = i & 127;
        int n = rem >> 3, j = rem & 7;
        int tap = chunk >> 1, half = chunk & 1;
        int kin = half * 16 + (j & ~1) + ((j & 1) << 3);
        float v0 = WG[(tap * CIN + kin) * CMID + n] * 1024.f;
        float v1 = WG[(tap * CIN + kin + 1) * CMID + n] * 1024.f;
        WbG[i] = f16x2pack(v1, v0);
    }
}

// ============ Kernel P: fp32 NCHW -> fp16 NHWC (k-interleaved order) =========
// pixel word layout (16 words): pos h*8+2i   <- chans (16h+2i,   16h+2i+1)
//                               pos h*8+2i+1 <- chans (16h+2i+8, 16h+2i+9)
__global__ void __launch_bounds__(256)
presplit_kernel(const float* __restrict__ x) {
    const int b = blockIdx.z, h = blockIdx.y, wx = blockIdx.x;
    const int tid = threadIdx.x;
    const int kq = tid & 7, wq = tid >> 3;
    const int hh = kq >> 2, i2 = kq & 3;
    const int c0 = hh * 16 + 2 * i2;
    const int w0 = wx * 128 + wq * 4;
    const int p0 = hh * 8 + 2 * i2;

    float v[4][4];
    const float* xp = x + (size_t)b * CIN * HW + (size_t)h * Wdim + w0;
    const int cset[4] = {c0, c0 + 1, c0 + 8, c0 + 9};
#pragma unroll
    for (int j = 0; j < 4; j++) {
        float4 f = *(const float4*)(xp + (size_t)cset[j] * HW);
        v[j][0] = f.x; v[j][1] = f.y; v[j][2] = f.z; v[j][3] = f.w;
    }
    unsigned short* base = xpkG + ((size_t)b * HW + (size_t)h * Wdim + w0) * CIN;
#pragma unroll
    for (int i = 0; i < 4; i++) {
        unsigned r0 = f16x2pack(v[1][i], v[0][i]);   // (c0, c0+1)
        unsigned r1 = f16x2pack(v[3][i], v[2][i]);   // (c0+8, c0+9)
        *(uint2*)(base + (size_t)i * CIN + p0 * 2) = make_uint2(r0, r1);
    }
}

// ================= Kernel C: HMMA implicit-GEMM conv + fp32 epilogue =========
__global__ void __launch_bounds__(256)
conv_kernel(float* __restrict__ out) {
    extern __shared__ __align__(16) char smem[];
    float*    xsw = (float*)(smem + SM_XSW);     // [484][24] words
    unsigned* bfr = (unsigned*)(smem + SM_BF);   // [50][16][8]
    float*    As  = (float*)(smem + SM_AS);      // [32][16] (prescaled /1024)
    float*    cons = (float*)(smem + SM_CONS);

    const int b  = blockIdx.z;
    const int tY = blockIdx.y, tX = blockIdx.x;
    const int tid  = threadIdx.x;
    const int w    = tid >> 5;
    const int lane = tid & 31;
    const int g    = lane >> 2;
    const int tg   = lane & 3;

    // ---- stage B fragments + epilogue constants
    {
        const uint4* sB = (const uint4*)WbG;
        uint4* dB = (uint4*)bfr;
        for (int i = tid; i < NCHUNK * 128 / 4; i += 256) dB[i] = sB[i];
        for (int i = tid; i < COUT * CMID; i += 256)
            As[i] = AG[b * COUT * CMID + i] * (1.f / 1024.f);
        if (tid < COUT) cons[tid] = constG[b * COUT + tid];
    }

    // ---- stage x window (22x22 px, 64B each, pitch-24 words)
    {
        const unsigned short* xb = xpkG + (size_t)b * HW * CIN;
        const int gh0 = tY * TPX - 3, gw0 = tX * TPX - 3;
        for (int idx = tid; idx < NPOS * 4; idx += 256) {
            int pos = idx >> 2, c = idx & 3;
            int r = pos / WPOS, cc = pos - r * WPOS;
            int gh = gh0 + r, gw = gw0 + cc;
            uint4 v = make_uint4(0, 0, 0, 0);
            if ((unsigned)gh < Hdim && (unsigned)gw < Wdim)
                v = *(const uint4*)(xb + ((size_t)gh * Wdim + gw) * CIN + c * 8);
            *(uint4*)(xsw + pos * PITCH + c * 4) = v;
        }
    }
    __syncthreads();

    // ---- mainloop: 50 chunks, fully unrolled, all-LDS.64
    float d[2][2][4];
#pragma unroll
    for (int mt = 0; mt < 2; mt++)
#pragma unroll
        for (int nt = 0; nt < 2; nt++)
#pragma unroll
            for (int q = 0; q < 4; q++) d[mt][nt][q] = 0.f;

    const uint2* Xw = (const uint2*)xsw;
    const uint2* Bw = (const uint2*)bfr;
    const int aidx = ((2 * w + 3) * WPOS + (g + 3)) * (PITCH / 2) + tg;
    const int bidx = g * 4 + tg;

#pragma unroll
    for (int chunk = 0; chunk < NCHUNK; chunk++) {
        const int tap = chunk >> 1, half = chunk & 1;
        const int wof = (tapy_c(tap) * WPOS + tapx_c(tap)) * (PITCH / 2) + half * 4;
        uint2 b0 = Bw[chunk * 64 + bidx];        // (b0,b1) for nt=0
        uint2 b1 = Bw[chunk * 64 + bidx + 32];   // (b0,b1) for nt=1
#pragma unroll
        for (int mt = 0; mt < 2; mt++) {
            const int ai = aidx + mt * (WPOS * PITCH / 2) + wof;
            uint2 aA = Xw[ai];                    // (a0, a2)  px = g
            uint2 aB = Xw[ai + 8 * (PITCH / 2)];  // (a1, a3)  px = g+8
            mma16816(d[mt][0], aA.x, aB.x, aA.y, aB.y, b0.x, b0.y);
            mma16816(d[mt][1], aA.x, aB.x, aA.y, aB.y, b1.x, b1.y);
        }
    }

    // ---- write T to smem (reuse window region), pitch 17
    __syncthreads();
    float* T = xsw;
#pragma unroll
    for (int mt = 0; mt < 2; mt++) {
        int p0 = 32 * w + 16 * mt + g;
#pragma unroll
        for (int nt = 0; nt < 2; nt++) {
            int c0 = 8 * nt + 2 * tg;
            T[p0 * 17 + c0]           = d[mt][nt][0];
            T[p0 * 17 + c0 + 1]       = d[mt][nt][1];
            T[(p0 + 8) * 17 + c0]     = d[mt][nt][2];
            T[(p0 + 8) * 17 + c0 + 1] = d[mt][nt][3];
        }
    }
    __syncthreads();

    // ---- fp32 epilogue: out[o] = cons[o] + sum_c As[o,c]*T[p,c]
    {
        const int p = tid;
        float Tl[CMID];
#pragma unroll
        for (int c = 0; c < CMID; c++) Tl[c] = T[p * 17 + c];
        const int gy = tY * TPX + (p >> 4), gx = tX * TPX + (p & 15);
        float* ob = out + (size_t)b * COUT * HW + (size_t)gy * Wdim + gx;
#pragma unroll 4
        for (int o = 0; o < COUT; o++) {
            float acc = cons[o];
            const float* Ao = As + o * CMID;
#pragma unroll
            for (int c = 0; c < CMID; c++) acc = fmaf(Ao[c], Tl[c], acc);
            ob[(size_t)o * HW] = acc;
        }
    }
}

// ================= launch ====================================================
extern "C" void kernel_launch(void* const* d_in, const int* in_sizes, int n_in,
                              void* d_out, int out_size) {
    (void)in_sizes; (void)n_in; (void)out_size;
    const float* x     = (const float*)d_in[0];
    const float* w1    = (const float*)d_in[1];
    const float* b1    = (const float*)d_in[2];
    const float* w2    = (const float*)d_in[3];
    const float* b2    = (const float*)d_in[4];
    const float* w3    = (const float*)d_in[5];
    const float* b3    = (const float*)d_in[6];
    const float* w4    = (const float*)d_in[7];
    const float* b4    = (const float*)d_in[8];
    const float* w5    = (const float*)d_in[9];
    const float* b5    = (const float*)d_in[10];
    const float* gcn_w = (const float*)d_in[11];
    const float* gcn_b = (const float*)d_in[12];
    const float* attn  = (const float*)d_in[13];
    const float* fw    = (const float*)d_in[14];
    const float* fb    = (const float*)d_in[15];
    float* out = (float*)d_out;

    cudaFuncSetAttribute(conv_kernel,
                         cudaFuncAttributeMaxDynamicSharedMemorySize, SMEM_TOTAL);

    presplit_kernel<<<dim3(3, Hdim, B_), 256>>>(x);
    stats_kernel<<<B_ * CIN, 512>>>(x);
    prep_kernel<<<1, 128>>>(w1, b1, w2, b2, w3, b3, w4, b4, w5, b5,
                            gcn_w, gcn_b, attn, fw, fb);
    conv_kernel<<<dim3(Wdim / TPX, Hdim / TPX, B_), 256, SMEM_TOTAL>>>(out);
}